// round 11
// baseline (speedup 1.0000x reference)
#include <cuda_runtime.h>
#include <cuda_bf16.h>
#include <stdint.h>
#include <math.h>

#define N_NODES 50000
#define N_EDGES 800000
#define HID     128
#define OUT_DIM 40
#define N_LAYERS 4
#define N_GRAPHS 128
#define SCAN_B  49           // ceil(50000/1024)
#define EDGE_BLOCKS 3125     // ceil(800000/256)
#define WPREP_ELEMS (8 * HID * HID)
#define WPREP_BLOCKS ((WPREP_ELEMS + 255) / 256)
#define MTILES ((N_NODES + 127) / 128)     // 391
#define PERSIST_GRID 148                   // one wave, 1 CTA/SM
#define FA_BLOCKS 148
#define FA_THREADS 1024

// ---------------- scratch (static device globals; zero-initialized at load) ----------------
__device__ float g_A[N_NODES * HID];                    // fp32 node features (layer output)
__device__ __nv_bfloat16 g_Bh[N_NODES * HID];           // agg output hi  (GEMM1 input)
__device__ __nv_bfloat16 g_Bl[N_NODES * HID];           // agg output lo
__device__ __nv_bfloat16 g_Ch[N_NODES * HID];           // GEMM1 output hi (GEMM2 input)
__device__ __nv_bfloat16 g_Cl[N_NODES * HID];           // GEMM1 output lo
__device__ __nv_bfloat16 g_Wth[WPREP_ELEMS];            // transposed weights hi: [mat][n][k]
__device__ __nv_bfloat16 g_Wtl[WPREP_ELEMS];            // transposed weights lo
__device__ int   g_rowoff[N_NODES + 1];                 // zeroed at load + k_pool tail
__device__ int   g_cursor[N_NODES];
__device__ int   g_srcs[N_EDGES];
__device__ volatile int g_bsum[SCAN_B];
__device__ volatile int g_bflag[SCAN_B];                // zeroed at load + k_pool tail
__device__ volatile int g_gbar;                         // fillagg grid barrier; reset in k_pool
__device__ int   g_is64;
__device__ float g_pooled[N_GRAPHS * HID];

// ---------------- helpers ----------------
__device__ __forceinline__ long long load_idx(const void* p, long long i, int is64) {
    if (is64) return ((const long long*)p)[i];
    return (long long)((const int*)p)[i];
}

__device__ __forceinline__ unsigned pack_bf(float a, float b) {
    __nv_bfloat162 t = __floats2bfloat162_rn(a, b);
    return *reinterpret_cast<unsigned*>(&t);
}

// ---------------- CSR count (by dst) + weight split/transpose (extra blocks) ----------------
__global__ void k_count(const void* __restrict__ edge,
                        const float* __restrict__ W1s, const float* __restrict__ W2s) {
    int b = blockIdx.x;
    if (b >= EDGE_BLOCKS) {
        // weight prep: Wt[mat][n][k] = W[mat][k][n] split into bf16 hi/lo
        int t = (b - EDGE_BLOCKS) * 256 + threadIdx.x;
        if (t < WPREP_ELEMS) {
            int mat = t >> 14, rem = t & 16383;
            int n = rem >> 7, k = rem & 127;
            int l = mat >> 1;
            float w = (mat & 1) ? W2s[l * 16384 + k * 128 + n]
                                : W1s[l * 16384 + k * 128 + n];
            __nv_bfloat16 h = __float2bfloat16(w);
            g_Wth[t] = h;
            g_Wtl[t] = __float2bfloat16(w - __bfloat162float(h));
        }
        return;
    }
    __shared__ int s_is64;
    int t = threadIdx.x;
    if (t == 0) s_is64 = 1;
    __syncthreads();
    if (t < 64) {
        // int32 data reinterpreted as int64 has a random node id in the high
        // word (invalid w.p. ~1), so 64 valid samples => genuine int64.
        long long v = ((const long long*)edge)[(long long)t * 12347 + 5];
        if (v < 0 || v >= N_NODES) atomicAnd(&s_is64, 0);
    }
    __syncthreads();
    int is64 = s_is64;
    if (b == 0 && t == 0) g_is64 = is64;
    int e = b * blockDim.x + t;
    if (e < N_EDGES) {
        int dst = (int)load_idx(edge, (long long)N_EDGES + e, is64);
        atomicAdd(&g_rowoff[dst], 1);
    }
}

// ---------------- single-kernel scan: block scan + decoupled lookback ----------------
__global__ void k_scanall() {
    __shared__ int part[1024];
    __shared__ int s_pref;
    int t = threadIdx.x, bid = blockIdx.x;
    int idx = bid * 1024 + t;
    int c = (idx < N_NODES) ? g_rowoff[idx] : 0;
    part[t] = c;
    __syncthreads();
    #pragma unroll
    for (int off = 1; off < 1024; off <<= 1) {
        int v = (t >= off) ? part[t - off] : 0;
        __syncthreads();
        part[t] += v;
        __syncthreads();
    }
    if (t == 1023) {
        g_bsum[bid] = part[1023];
        __threadfence();
        g_bflag[bid] = 1;
    }
    if (t < 32) {
        int s = 0;
        for (int p = t; p < bid; p += 32) {
            while (g_bflag[p] == 0) { }
            s += g_bsum[p];
        }
        #pragma unroll
        for (int o = 16; o; o >>= 1) s += __shfl_xor_sync(0xffffffffu, s, o);
        if (t == 0) s_pref = s;
    }
    __syncthreads();
    int pref = s_pref;
    if (idx < N_NODES) {
        int v = pref + part[t] - c;
        g_rowoff[idx] = v;
        g_cursor[idx] = v;
    }
    if (bid == SCAN_B - 1 && t == 1023) g_rowoff[N_NODES] = N_EDGES;
}

// ---------------- shared aggregation body ----------------
// h[w] = (1+eps)*x[w] + sum_{src->w} x[src], emitted as bf16 hi/lo
template <int U>
__device__ __forceinline__ void agg_node(const float4* __restrict__ x4, int w, int lane,
                                         float eps,
                                         __nv_bfloat16* __restrict__ oh,
                                         __nv_bfloat16* __restrict__ ol) {
    float4 a = x4[(long long)w * 32 + lane];
    float ax = a.x * eps, ay = a.y * eps, az = a.z * eps, aw = a.w * eps;
    int e = g_rowoff[w], end = g_rowoff[w + 1];
    for (; e + U - 1 < end; e += U) {
        int ss[U];
        float4 vv[U];
        #pragma unroll
        for (int j = 0; j < U; j++) ss[j] = g_srcs[e + j];
        #pragma unroll
        for (int j = 0; j < U; j++) vv[j] = x4[(long long)ss[j] * 32 + lane];
        #pragma unroll
        for (int j = 0; j < U; j++) {
            ax += vv[j].x; ay += vv[j].y; az += vv[j].z; aw += vv[j].w;
        }
    }
    for (; e < end; e++) {
        int s = g_srcs[e];
        float4 v = x4[(long long)s * 32 + lane];
        ax += v.x; ay += v.y; az += v.z; aw += v.w;
    }
    float hx = __bfloat162float(__float2bfloat16(ax));
    float hy = __bfloat162float(__float2bfloat16(ay));
    float hz = __bfloat162float(__float2bfloat16(az));
    float hw = __bfloat162float(__float2bfloat16(aw));
    uint2 H = make_uint2(pack_bf(hx, hy), pack_bf(hz, hw));
    uint2 L = make_uint2(pack_bf(ax - hx, ay - hy), pack_bf(az - hz, aw - hw));
    *(uint2*)(oh + (long long)w * 128 + lane * 4) = H;
    *(uint2*)(ol + (long long)w * 128 + lane * 4) = L;
}

// ---------------- fused CSR-fill + layer-0 aggregation (persistent, grid barrier) ----------------
// 148 blocks x 1024 threads, no smem -> guaranteed co-resident, so the internal
// spin barrier cannot deadlock. Phase 1 scatters srcs; phase 2 aggregates layer 0.
__global__ void __launch_bounds__(FA_THREADS, 1)
k_fillagg(const void* __restrict__ edge, const float* __restrict__ xin,
          __nv_bfloat16* __restrict__ oh, __nv_bfloat16* __restrict__ ol,
          const float* __restrict__ eps_arr) {
    int tid = threadIdx.x;
    int gid = blockIdx.x * FA_THREADS + tid;
    int is64 = g_is64;
    // phase 1: fill CSR srcs
    for (int e = gid; e < N_EDGES; e += FA_BLOCKS * FA_THREADS) {
        int src = (int)load_idx(edge, e, is64);
        int dst = (int)load_idx(edge, (long long)N_EDGES + e, is64);
        int pos = atomicAdd(&g_cursor[dst], 1);
        g_srcs[pos] = src;
    }
    // grid barrier (g_gbar is 0 at entry: zero-init at load, reset by k_pool)
    __syncthreads();
    if (tid == 0) {
        __threadfence();
        atomicAdd((int*)&g_gbar, 1);
        while (g_gbar < FA_BLOCKS) { }
    }
    __syncthreads();
    __threadfence();
    // phase 2: layer-0 aggregation
    float eps = 1.0f + eps_arr[0];
    const float4* x4 = (const float4*)xin;
    int gw = gid >> 5, lane = tid & 31;
    const int NW = (FA_BLOCKS * FA_THREADS) / 32;   // 4736 warps
    for (int w = gw; w < N_NODES; w += NW)
        agg_node<4>(x4, w, lane, eps, oh, ol);
}

// ---------------- standalone aggregation (layers 1-3) ----------------
__global__ void k_agg(const float* __restrict__ xin,
                      __nv_bfloat16* __restrict__ oh, __nv_bfloat16* __restrict__ ol,
                      const float* __restrict__ eps_arr, int layer) {
    int w = (blockIdx.x * blockDim.x + threadIdx.x) >> 5;
    int lane = threadIdx.x & 31;
    if (w >= N_NODES) return;
    float eps = 1.0f + eps_arr[layer];
    agg_node<8>((const float4*)xin, w, lane, eps, oh, ol);
}

// ---------------- persistent HMMA GEMM with cp.async double-buffered A ----------------
// 148 CTAs, each loops over M tiles (bid, bid+148, ...). Per tile:
// D[128,128] = A[128,128] @ Wt^T with hi/lo compensation (Ah*Wh + Ah*Wl + Al*Wh).
// W hi/lo staged ONCE per CTA; A hi/lo for tile t+1 prefetched via cp.async.cg
// while tile t computes. smem rows padded to 272 B (conflict-free ldmatrix).

#define ASTR_B 272                      // padded row stride in bytes (136 bf16)
#define MAT_B (128 * ASTR_B)            // 34816 B per 128x128 matrix
#define SM_WH 0
#define SM_WL MAT_B
#define SM_ABUF(i) (2 * MAT_B + (i) * (2 * MAT_B))   // Ah then Al inside each buffer
#define SM_TOTAL (6 * MAT_B)            // 208896 B -> 1 CTA/SM

__device__ __forceinline__ void ldsm4(unsigned* r, unsigned addr) {
    asm volatile("ldmatrix.sync.aligned.m8n8.x4.shared.b16 {%0,%1,%2,%3}, [%4];"
                 : "=r"(r[0]), "=r"(r[1]), "=r"(r[2]), "=r"(r[3]) : "r"(addr));
}
__device__ __forceinline__ void ldsm2(unsigned* r, unsigned addr) {
    asm volatile("ldmatrix.sync.aligned.m8n8.x2.shared.b16 {%0,%1}, [%2];"
                 : "=r"(r[0]), "=r"(r[1]) : "r"(addr));
}
__device__ __forceinline__ void mma_bf16(float* d, const unsigned* a, const unsigned* b) {
    asm volatile("mma.sync.aligned.m16n8k16.row.col.f32.bf16.bf16.f32 "
                 "{%0,%1,%2,%3}, {%4,%5,%6,%7}, {%8,%9}, {%0,%1,%2,%3};"
                 : "+f"(d[0]), "+f"(d[1]), "+f"(d[2]), "+f"(d[3])
                 : "r"(a[0]), "r"(a[1]), "r"(a[2]), "r"(a[3]), "r"(b[0]), "r"(b[1]));
}
__device__ __forceinline__ void cp16(unsigned saddr, const void* g, int nbytes) {
    asm volatile("cp.async.cg.shared.global [%0], [%1], 16, %2;"
                 :: "r"(saddr), "l"(g), "r"(nbytes) : "memory");
}

// issue cp.asyncs for one 128x128 bf16 A tile (hi+lo) into buffer at sbuf
__device__ __forceinline__ void issue_A(const __nv_bfloat16* __restrict__ Ah,
                                        const __nv_bfloat16* __restrict__ Al,
                                        int row0, unsigned sbuf, int tid) {
    #pragma unroll
    for (int it = 0; it < 8; it++) {
        int i = tid + it * 256;                  // 0..2047 16B chunks
        int r = i >> 4, c16 = i & 15;
        bool ok = (row0 + r) < N_NODES;
        const char* gh = (const char*)(Ah + (long long)(row0 + r) * 128) + c16 * 16;
        const char* gl = (const char*)(Al + (long long)(row0 + r) * 128) + c16 * 16;
        unsigned d = sbuf + (unsigned)(r * ASTR_B + c16 * 16);
        cp16(d, ok ? gh : (const char*)Ah, ok ? 16 : 0);
        cp16(d + MAT_B, ok ? gl : (const char*)Al, ok ? 16 : 0);
    }
}

__global__ void __launch_bounds__(256, 1)
k_mma(const __nv_bfloat16* __restrict__ Ah, const __nv_bfloat16* __restrict__ Al,
      const __nv_bfloat16* __restrict__ Wh, const __nv_bfloat16* __restrict__ Wl,
      const float* __restrict__ bias,
      float* __restrict__ outf,
      __nv_bfloat16* __restrict__ outh, __nv_bfloat16* __restrict__ outl,
      const float* __restrict__ gamma, const float* __restrict__ beta,
      const float* __restrict__ mean,  const float* __restrict__ var) {
    extern __shared__ char smem[];
    unsigned sb;
    asm("{ .reg .u64 t; cvta.to.shared.u64 t, %1; cvt.u32.u64 %0, t; }" : "=r"(sb) : "l"(smem));
    int tid = threadIdx.x, wid = tid >> 5, lane = tid & 31;

    // stage W hi/lo once + prefetch first A tile (single commit group)
    #pragma unroll
    for (int it = 0; it < 8; it++) {
        int i = tid + it * 256;
        int r = i >> 4, c16 = i & 15;
        unsigned off = (unsigned)(r * ASTR_B + c16 * 16);
        cp16(sb + SM_WH + off, (const char*)(Wh + (long long)r * 128) + c16 * 16, 16);
        cp16(sb + SM_WL + off, (const char*)(Wl + (long long)r * 128) + c16 * 16, 16);
    }
    int tile = blockIdx.x;
    if (tile < MTILES) issue_A(Ah, Al, tile * 128, sb + SM_ABUF(0), tid);
    asm volatile("cp.async.commit_group;" ::: "memory");

    // per-warp constants (columns don't depend on tile)
    int wr = wid & 3, wc = wid >> 2;      // warp tile: rows wr*32..+32, cols wc*64..+64
    int quad = lane >> 2, qi = lane & 3;
    float bcol[16], scv[16], shv[16];
    bool bn = (gamma != nullptr);
    #pragma unroll
    for (int nt = 0; nt < 8; nt++) {
        int c = wc * 64 + nt * 8 + qi * 2;
        bcol[nt * 2]     = __ldg(bias + c);
        bcol[nt * 2 + 1] = __ldg(bias + c + 1);
        if (bn) {
            float s0 = __ldg(gamma + c) * rsqrtf(__ldg(var + c) + 1e-5f);
            float s1 = __ldg(gamma + c + 1) * rsqrtf(__ldg(var + c + 1) + 1e-5f);
            scv[nt * 2] = s0;     shv[nt * 2]     = __ldg(beta + c) - __ldg(mean + c) * s0;
            scv[nt * 2 + 1] = s1; shv[nt * 2 + 1] = __ldg(beta + c + 1) - __ldg(mean + c + 1) * s1;
        }
    }

    // ldmatrix lane address components
    unsigned aoff = (unsigned)((wr * 32 + (lane & 15)) * ASTR_B + (lane >> 4) * 16);
    int l16 = lane & 15;
    unsigned boff = (unsigned)((wc * 64 + (l16 & 7)) * ASTR_B + ((l16 >> 3) & 1) * 16);
    unsigned bH = sb + SM_WH + boff, bL = sb + SM_WL + boff;

    int bufi = 0;
    for (; tile < MTILES; tile += PERSIST_GRID, bufi ^= 1) {
        asm volatile("cp.async.wait_group 0;" ::: "memory");
        __syncthreads();
        int next = tile + PERSIST_GRID;
        if (next < MTILES) issue_A(Ah, Al, next * 128, sb + SM_ABUF(bufi ^ 1), tid);
        asm volatile("cp.async.commit_group;" ::: "memory");

        unsigned abase = sb + SM_ABUF(bufi);
        unsigned aH0 = abase + aoff, aH1 = aH0 + 16 * ASTR_B;
        unsigned aL0 = abase + MAT_B + aoff, aL1 = aL0 + 16 * ASTR_B;

        float acc[2][8][4];
        #pragma unroll
        for (int mt = 0; mt < 2; mt++)
            #pragma unroll
            for (int nt = 0; nt < 8; nt++)
                #pragma unroll
                for (int j = 0; j < 4; j++) acc[mt][nt][j] = 0.f;

        #pragma unroll
        for (int ks = 0; ks < 8; ks++) {
            unsigned kb = (unsigned)(ks * 32);            // k0 * 2 bytes
            unsigned ah[2][4], al[2][4], bh[8][2], bl[8][2];
            ldsm4(ah[0], aH0 + kb);
            ldsm4(ah[1], aH1 + kb);
            ldsm4(al[0], aL0 + kb);
            ldsm4(al[1], aL1 + kb);
            #pragma unroll
            for (int nt = 0; nt < 8; nt++) {
                ldsm2(bh[nt], bH + (unsigned)(nt * 8 * ASTR_B) + kb);
                ldsm2(bl[nt], bL + (unsigned)(nt * 8 * ASTR_B) + kb);
            }
            #pragma unroll
            for (int mt = 0; mt < 2; mt++)
                #pragma unroll
                for (int nt = 0; nt < 8; nt++) {
                    mma_bf16(acc[mt][nt], ah[mt], bh[nt]);
                    mma_bf16(acc[mt][nt], ah[mt], bl[nt]);
                    mma_bf16(acc[mt][nt], al[mt], bh[nt]);
                }
        }

        // epilogue: C frag m16n8 -> rows quad, quad+8; cols qi*2, qi*2+1
        int row0 = tile * 128;
        #pragma unroll
        for (int mt = 0; mt < 2; mt++) {
            int r0 = row0 + wr * 32 + mt * 16 + quad;
            #pragma unroll
            for (int half = 0; half < 2; half++) {
                int r = r0 + half * 8;
                if (r >= N_NODES) continue;
                #pragma unroll
                for (int nt = 0; nt < 8; nt++) {
                    int c = wc * 64 + nt * 8 + qi * 2;
                    float d0 = acc[mt][nt][half * 2], d1 = acc[mt][nt][half * 2 + 1];
                    float v0 = fmaxf(d0 + bcol[nt * 2], 0.f);
                    float v1 = fmaxf(d1 + bcol[nt * 2 + 1], 0.f);
                    if (outf) {
                        if (bn) {
                            v0 = v0 * scv[nt * 2] + shv[nt * 2];
                            v1 = v1 * scv[nt * 2 + 1] + shv[nt * 2 + 1];
                        }
                        *(float2*)(outf + (long long)r * 128 + c) = make_float2(v0, v1);
                    } else {
                        float h0 = __bfloat162float(__float2bfloat16(v0));
                        float h1 = __bfloat162float(__float2bfloat16(v1));
                        *(unsigned*)(outh + (long long)r * 128 + c) = pack_bf(h0, h1);
                        *(unsigned*)(outl + (long long)r * 128 + c) = pack_bf(v0 - h0, v1 - h1);
                    }
                }
            }
        }
    }
}

// ---------------- mean pool per graph (batch sorted) + scratch reset tail ----------------
__device__ __forceinline__ int lower_bound_batch(const void* batch, long long key, int is64) {
    int lo = 0, hi = N_NODES;
    while (lo < hi) {
        int mid = (lo + hi) >> 1;
        long long v = load_idx(batch, mid, is64);
        if (v < key) lo = mid + 1; else hi = mid;
    }
    return lo;
}

__global__ void k_pool(const float* __restrict__ x, const void* __restrict__ batch) {
    int g = blockIdx.x;
    int f = threadIdx.x;
    __shared__ int s_beg, s_end;
    if (f == 0) {
        int is64 = g_is64;
        s_beg = lower_bound_batch(batch, g, is64);
        s_end = lower_bound_batch(batch, g + 1, is64);
    }
    __syncthreads();
    int beg = s_beg, end = s_end;
    float s = 0.f;
    for (int r = beg; r < end; r++) s += x[(long long)r * HID + f];
    float cnt = (float)(end - beg);
    g_pooled[g * HID + f] = s / fmaxf(cnt, 1.0f);

    // tail: reset CSR scratch + barriers for the next graph replay
    int gt = g * HID + f;
    for (int i = gt; i < N_NODES + 1; i += N_GRAPHS * HID) g_rowoff[i] = 0;
    if (gt < SCAN_B) g_bflag[gt] = 0;
    if (gt == 0) g_gbar = 0;
}

// ---------------- head: relu(pooled@W1+b1) @ W2 + b2, log_softmax ----------------
__global__ void k_head(const float* __restrict__ W1, const float* __restrict__ b1,
                       const float* __restrict__ W2, const float* __restrict__ b2,
                       float* __restrict__ out) {
    int g = blockIdx.x;
    int t = threadIdx.x;
    __shared__ float sp[HID], sh[HID], sl[OUT_DIM];
    __shared__ float smax, slse;
    sp[t] = g_pooled[g * HID + t];
    __syncthreads();
    float acc = b1[t];
    #pragma unroll 8
    for (int k = 0; k < HID; k++) acc += sp[k] * W1[k * HID + t];
    sh[t] = fmaxf(acc, 0.f);
    __syncthreads();
    if (t < OUT_DIM) {
        float a = b2[t];
        #pragma unroll 8
        for (int k = 0; k < HID; k++) a += sh[k] * W2[k * OUT_DIM + t];
        sl[t] = a;
    }
    __syncthreads();
    if (t == 0) {
        float m = -1e30f;
        for (int o = 0; o < OUT_DIM; o++) m = fmaxf(m, sl[o]);
        float s = 0.f;
        for (int o = 0; o < OUT_DIM; o++) s += expf(sl[o] - m);
        smax = m; slse = logf(s);
    }
    __syncthreads();
    if (t < OUT_DIM) out[g * OUT_DIM + t] = sl[t] - smax - slse;
}

// ---------------- launch ----------------
extern "C" void kernel_launch(void* const* d_in, const int* in_sizes, int n_in,
                              void* d_out, int out_size) {
    const float* x      = (const float*)d_in[0];
    const void*  edge   = d_in[1];
    const void*  batch  = d_in[2];
    const float* W1s    = (const float*)d_in[3];
    const float* b1s    = (const float*)d_in[4];
    const float* W2s    = (const float*)d_in[5];
    const float* b2s    = (const float*)d_in[6];
    const float* gammas = (const float*)d_in[7];
    const float* betas  = (const float*)d_in[8];
    const float* means  = (const float*)d_in[9];
    const float* vars   = (const float*)d_in[10];
    const float* epsarr = (const float*)d_in[11];
    const float* lin1W  = (const float*)d_in[12];
    const float* lin1b  = (const float*)d_in[13];
    const float* lin2W  = (const float*)d_in[14];
    const float* lin2b  = (const float*)d_in[15];
    float* out = (float*)d_out;

    float *A;
    __nv_bfloat16 *Bh, *Bl, *Ch, *Cl, *Wth, *Wtl;
    cudaGetSymbolAddress((void**)&A,  g_A);
    cudaGetSymbolAddress((void**)&Bh, g_Bh);
    cudaGetSymbolAddress((void**)&Bl, g_Bl);
    cudaGetSymbolAddress((void**)&Ch, g_Ch);
    cudaGetSymbolAddress((void**)&Cl, g_Cl);
    cudaGetSymbolAddress((void**)&Wth, g_Wth);
    cudaGetSymbolAddress((void**)&Wtl, g_Wtl);

    cudaFuncSetAttribute(k_mma, cudaFuncAttributeMaxDynamicSharedMemorySize, SM_TOTAL);

    // CSR build + weight prep; fillagg fuses fill with layer-0 agg so that
    // k_mma is launch #4 (the ncu capture slot)
    k_count<<<EDGE_BLOCKS + WPREP_BLOCKS, 256>>>(edge, W1s, W2s);
    k_scanall<<<SCAN_B, 1024>>>();
    k_fillagg<<<FA_BLOCKS, FA_THREADS>>>(edge, x, Bh, Bl, epsarr);

    const int agg_blocks = (N_NODES * 32 + 255) / 256;

    for (int l = 0; l < N_LAYERS; l++) {
        if (l > 0)
            k_agg<<<agg_blocks, 256>>>(A, Bh, Bl, epsarr, l);
        // GEMM1: relu -> bf16 hi/lo
        k_mma<<<PERSIST_GRID, 256, SM_TOTAL>>>(
            Bh, Bl, Wth + (l * 2) * 16384, Wtl + (l * 2) * 16384,
            b1s + l * HID, nullptr, Ch, Cl,
            nullptr, nullptr, nullptr, nullptr);
        // GEMM2: relu + BN -> fp32
        k_mma<<<PERSIST_GRID, 256, SM_TOTAL>>>(
            Ch, Cl, Wth + (l * 2 + 1) * 16384, Wtl + (l * 2 + 1) * 16384,
            b2s + l * HID, A, nullptr, nullptr,
            gammas + l * HID, betas + l * HID, means + l * HID, vars + l * HID);
    }

    k_pool<<<N_GRAPHS, HID>>>(A, batch);
    k_head<<<N_GRAPHS, HID>>>(lin1W, lin1b, lin2W, lin2b, out);
}

// round 12
// speedup vs baseline: 1.0148x; 1.0148x over previous
#include <cuda_runtime.h>
#include <cuda_bf16.h>
#include <stdint.h>
#include <math.h>

#define N_NODES 50000
#define N_EDGES 800000
#define HID     128
#define OUT_DIM 40
#define N_LAYERS 4
#define N_GRAPHS 128
#define SCAN_B  49           // ceil(50000/1024)
#define EDGE_BLOCKS 3125     // ceil(800000/256)
#define WPREP_ELEMS (8 * HID * HID)
#define WPREP_BLOCKS ((WPREP_ELEMS + 255) / 256)
#define MTILES ((N_NODES + 127) / 128)     // 391
#define PERSIST_GRID 148                   // one wave, 1 CTA/SM
#define FA_BLOCKS 148
#define FA_THREADS 1024

// ---------------- scratch (static device globals; zero-initialized at load) ----------------
__device__ float g_A[N_NODES * HID];                    // fp32 node features (layer output)
__device__ __nv_bfloat16 g_Bh[N_NODES * HID];           // agg output hi  (GEMM1 input)
__device__ __nv_bfloat16 g_Bl[N_NODES * HID];           // agg output lo
__device__ __nv_bfloat16 g_Ch[N_NODES * HID];           // GEMM1 output hi (GEMM2 input)
__device__ __nv_bfloat16 g_Cl[N_NODES * HID];           // GEMM1 output lo
__device__ __nv_bfloat16 g_Wth[WPREP_ELEMS];            // transposed weights hi: [mat][n][k]
__device__ __nv_bfloat16 g_Wtl[WPREP_ELEMS];            // transposed weights lo
__device__ int   g_rowoff[N_NODES + 1];                 // zeroed at load + k_pool tail
__device__ int   g_cursor[N_NODES];
__device__ int   g_srcs[N_EDGES];
__device__ volatile int g_bsum[SCAN_B];
__device__ volatile int g_bflag[SCAN_B];                // zeroed at load + k_pool tail
__device__ volatile int g_gbar;                         // fillagg grid barrier; reset in k_pool
__device__ int   g_is64;
__device__ float g_pooled[N_GRAPHS * HID];

// ---------------- helpers ----------------
__device__ __forceinline__ long long load_idx(const void* p, long long i, int is64) {
    if (is64) return ((const long long*)p)[i];
    return (long long)((const int*)p)[i];
}

__device__ __forceinline__ unsigned pack_bf(float a, float b) {
    __nv_bfloat162 t = __floats2bfloat162_rn(a, b);
    return *reinterpret_cast<unsigned*>(&t);
}

// ---------------- CSR count (by dst) + weight split/transpose (extra blocks) ----------------
__global__ void k_count(const void* __restrict__ edge,
                        const float* __restrict__ W1s, const float* __restrict__ W2s) {
    int b = blockIdx.x;
    if (b >= EDGE_BLOCKS) {
        // weight prep: Wt[mat][n][k] = W[mat][k][n] split into bf16 hi/lo
        int t = (b - EDGE_BLOCKS) * 256 + threadIdx.x;
        if (t < WPREP_ELEMS) {
            int mat = t >> 14, rem = t & 16383;
            int n = rem >> 7, k = rem & 127;
            int l = mat >> 1;
            float w = (mat & 1) ? W2s[l * 16384 + k * 128 + n]
                                : W1s[l * 16384 + k * 128 + n];
            __nv_bfloat16 h = __float2bfloat16(w);
            g_Wth[t] = h;
            g_Wtl[t] = __float2bfloat16(w - __bfloat162float(h));
        }
        return;
    }
    __shared__ int s_is64;
    int t = threadIdx.x;
    if (t == 0) s_is64 = 1;
    __syncthreads();
    if (t < 64) {
        // int32 data reinterpreted as int64 has a random node id in the high
        // word (invalid w.p. ~1), so 64 valid samples => genuine int64.
        long long v = ((const long long*)edge)[(long long)t * 12347 + 5];
        if (v < 0 || v >= N_NODES) atomicAnd(&s_is64, 0);
    }
    __syncthreads();
    int is64 = s_is64;
    if (b == 0 && t == 0) g_is64 = is64;
    int e = b * blockDim.x + t;
    if (e < N_EDGES) {
        int dst = (int)load_idx(edge, (long long)N_EDGES + e, is64);
        atomicAdd(&g_rowoff[dst], 1);
    }
}

// ---------------- single-kernel scan: block scan + decoupled lookback ----------------
__global__ void k_scanall() {
    __shared__ int part[1024];
    __shared__ int s_pref;
    int t = threadIdx.x, bid = blockIdx.x;
    int idx = bid * 1024 + t;
    int c = (idx < N_NODES) ? g_rowoff[idx] : 0;
    part[t] = c;
    __syncthreads();
    #pragma unroll
    for (int off = 1; off < 1024; off <<= 1) {
        int v = (t >= off) ? part[t - off] : 0;
        __syncthreads();
        part[t] += v;
        __syncthreads();
    }
    if (t == 1023) {
        g_bsum[bid] = part[1023];
        __threadfence();
        g_bflag[bid] = 1;
    }
    if (t < 32) {
        int s = 0;
        for (int p = t; p < bid; p += 32) {
            while (g_bflag[p] == 0) { }
            s += g_bsum[p];
        }
        #pragma unroll
        for (int o = 16; o; o >>= 1) s += __shfl_xor_sync(0xffffffffu, s, o);
        if (t == 0) s_pref = s;
    }
    __syncthreads();
    int pref = s_pref;
    if (idx < N_NODES) {
        int v = pref + part[t] - c;
        g_rowoff[idx] = v;
        g_cursor[idx] = v;
    }
    if (bid == SCAN_B - 1 && t == 1023) g_rowoff[N_NODES] = N_EDGES;
}

// ---------------- shared aggregation body ----------------
// h[w] = (1+eps)*x[w] + sum_{src->w} x[src], emitted as bf16 hi/lo
template <int U>
__device__ __forceinline__ void agg_node(const float4* __restrict__ x4, int w, int lane,
                                         float eps,
                                         __nv_bfloat16* __restrict__ oh,
                                         __nv_bfloat16* __restrict__ ol) {
    float4 a = x4[(long long)w * 32 + lane];
    float ax = a.x * eps, ay = a.y * eps, az = a.z * eps, aw = a.w * eps;
    int e = g_rowoff[w], end = g_rowoff[w + 1];
    for (; e + U - 1 < end; e += U) {
        int ss[U];
        float4 vv[U];
        #pragma unroll
        for (int j = 0; j < U; j++) ss[j] = g_srcs[e + j];
        #pragma unroll
        for (int j = 0; j < U; j++) vv[j] = x4[(long long)ss[j] * 32 + lane];
        #pragma unroll
        for (int j = 0; j < U; j++) {
            ax += vv[j].x; ay += vv[j].y; az += vv[j].z; aw += vv[j].w;
        }
    }
    for (; e < end; e++) {
        int s = g_srcs[e];
        float4 v = x4[(long long)s * 32 + lane];
        ax += v.x; ay += v.y; az += v.z; aw += v.w;
    }
    float hx = __bfloat162float(__float2bfloat16(ax));
    float hy = __bfloat162float(__float2bfloat16(ay));
    float hz = __bfloat162float(__float2bfloat16(az));
    float hw = __bfloat162float(__float2bfloat16(aw));
    uint2 H = make_uint2(pack_bf(hx, hy), pack_bf(hz, hw));
    uint2 L = make_uint2(pack_bf(ax - hx, ay - hy), pack_bf(az - hz, aw - hw));
    *(uint2*)(oh + (long long)w * 128 + lane * 4) = H;
    *(uint2*)(ol + (long long)w * 128 + lane * 4) = L;
}

// ---------------- fused CSR-fill + layer-0 aggregation (persistent, grid barrier) ----------------
__global__ void __launch_bounds__(FA_THREADS, 1)
k_fillagg(const void* __restrict__ edge, const float* __restrict__ xin,
          __nv_bfloat16* __restrict__ oh, __nv_bfloat16* __restrict__ ol,
          const float* __restrict__ eps_arr) {
    int tid = threadIdx.x;
    int gid = blockIdx.x * FA_THREADS + tid;
    int is64 = g_is64;
    // phase 1: fill CSR srcs
    for (int e = gid; e < N_EDGES; e += FA_BLOCKS * FA_THREADS) {
        int src = (int)load_idx(edge, e, is64);
        int dst = (int)load_idx(edge, (long long)N_EDGES + e, is64);
        int pos = atomicAdd(&g_cursor[dst], 1);
        g_srcs[pos] = src;
    }
    // grid barrier (g_gbar is 0 at entry: zero-init at load, reset by k_pool)
    __syncthreads();
    if (tid == 0) {
        __threadfence();
        atomicAdd((int*)&g_gbar, 1);
        while (g_gbar < FA_BLOCKS) { }
    }
    __syncthreads();
    __threadfence();
    // phase 2: layer-0 aggregation
    float eps = 1.0f + eps_arr[0];
    const float4* x4 = (const float4*)xin;
    int gw = gid >> 5, lane = tid & 31;
    const int NW = (FA_BLOCKS * FA_THREADS) / 32;   // 4736 warps
    for (int w = gw; w < N_NODES; w += NW)
        agg_node<4>(x4, w, lane, eps, oh, ol);
}

// ---------------- standalone aggregation (layers 1-3) ----------------
__global__ void k_agg(const float* __restrict__ xin,
                      __nv_bfloat16* __restrict__ oh, __nv_bfloat16* __restrict__ ol,
                      const float* __restrict__ eps_arr, int layer) {
    int w = (blockIdx.x * blockDim.x + threadIdx.x) >> 5;
    int lane = threadIdx.x & 31;
    if (w >= N_NODES) return;
    float eps = 1.0f + eps_arr[layer];
    agg_node<8>((const float4*)xin, w, lane, eps, oh, ol);
}

// ---------------- persistent HMMA GEMM with cp.async double-buffered A ----------------
// 148 CTAs, each loops over M tiles. Per tile: D[128,128] = A @ Wt^T with hi/lo
// compensation. MAINLOOP IS COMBO-MAJOR: all 16 independent AhWh MMAs, then all
// AhWl, then all AlWh — dependent writes to the same accumulator are 16 issue
// slots apart, so asm-volatile program order no longer serializes on RAW chains.

#define ASTR_B 272                      // padded row stride in bytes (136 bf16)
#define MAT_B (128 * ASTR_B)            // 34816 B per 128x128 matrix
#define SM_WH 0
#define SM_WL MAT_B
#define SM_ABUF(i) (2 * MAT_B + (i) * (2 * MAT_B))   // Ah then Al inside each buffer
#define SM_TOTAL (6 * MAT_B)            // 208896 B -> 1 CTA/SM

__device__ __forceinline__ void ldsm4(unsigned* r, unsigned addr) {
    asm volatile("ldmatrix.sync.aligned.m8n8.x4.shared.b16 {%0,%1,%2,%3}, [%4];"
                 : "=r"(r[0]), "=r"(r[1]), "=r"(r[2]), "=r"(r[3]) : "r"(addr));
}
__device__ __forceinline__ void mma_bf16(float* d, const unsigned* a, const unsigned* b) {
    asm volatile("mma.sync.aligned.m16n8k16.row.col.f32.bf16.bf16.f32 "
                 "{%0,%1,%2,%3}, {%4,%5,%6,%7}, {%8,%9}, {%0,%1,%2,%3};"
                 : "+f"(d[0]), "+f"(d[1]), "+f"(d[2]), "+f"(d[3])
                 : "r"(a[0]), "r"(a[1]), "r"(a[2]), "r"(a[3]), "r"(b[0]), "r"(b[1]));
}
__device__ __forceinline__ void cp16(unsigned saddr, const void* g, int nbytes) {
    asm volatile("cp.async.cg.shared.global [%0], [%1], 16, %2;"
                 :: "r"(saddr), "l"(g), "r"(nbytes) : "memory");
}

// issue cp.asyncs for one 128x128 bf16 A tile (hi+lo) into buffer at sbuf
__device__ __forceinline__ void issue_A(const __nv_bfloat16* __restrict__ Ah,
                                        const __nv_bfloat16* __restrict__ Al,
                                        int row0, unsigned sbuf, int tid) {
    #pragma unroll
    for (int it = 0; it < 8; it++) {
        int i = tid + it * 256;                  // 0..2047 16B chunks
        int r = i >> 4, c16 = i & 15;
        bool ok = (row0 + r) < N_NODES;
        const char* gh = (const char*)(Ah + (long long)(row0 + r) * 128) + c16 * 16;
        const char* gl = (const char*)(Al + (long long)(row0 + r) * 128) + c16 * 16;
        unsigned d = sbuf + (unsigned)(r * ASTR_B + c16 * 16);
        cp16(d, ok ? gh : (const char*)Ah, ok ? 16 : 0);
        cp16(d + MAT_B, ok ? gl : (const char*)Al, ok ? 16 : 0);
    }
}

__global__ void __launch_bounds__(256, 1)
k_mma(const __nv_bfloat16* __restrict__ Ah, const __nv_bfloat16* __restrict__ Al,
      const __nv_bfloat16* __restrict__ Wh, const __nv_bfloat16* __restrict__ Wl,
      const float* __restrict__ bias,
      float* __restrict__ outf,
      __nv_bfloat16* __restrict__ outh, __nv_bfloat16* __restrict__ outl,
      const float* __restrict__ gamma, const float* __restrict__ beta,
      const float* __restrict__ mean,  const float* __restrict__ var) {
    extern __shared__ char smem[];
    unsigned sb;
    asm("{ .reg .u64 t; cvta.to.shared.u64 t, %1; cvt.u32.u64 %0, t; }" : "=r"(sb) : "l"(smem));
    int tid = threadIdx.x, wid = tid >> 5, lane = tid & 31;

    // stage W hi/lo once + prefetch first A tile (single commit group)
    #pragma unroll
    for (int it = 0; it < 8; it++) {
        int i = tid + it * 256;
        int r = i >> 4, c16 = i & 15;
        unsigned off = (unsigned)(r * ASTR_B + c16 * 16);
        cp16(sb + SM_WH + off, (const char*)(Wh + (long long)r * 128) + c16 * 16, 16);
        cp16(sb + SM_WL + off, (const char*)(Wl + (long long)r * 128) + c16 * 16, 16);
    }
    int tile = blockIdx.x;
    if (tile < MTILES) issue_A(Ah, Al, tile * 128, sb + SM_ABUF(0), tid);
    asm volatile("cp.async.commit_group;" ::: "memory");

    // per-warp constants (columns don't depend on tile)
    int wr = wid & 3, wc = wid >> 2;      // warp tile: rows wr*32..+32, cols wc*64..+64
    int quad = lane >> 2, qi = lane & 3;
    float bcol[16], scv[16], shv[16];
    bool bn = (gamma != nullptr);
    #pragma unroll
    for (int nt = 0; nt < 8; nt++) {
        int c = wc * 64 + nt * 8 + qi * 2;
        bcol[nt * 2]     = __ldg(bias + c);
        bcol[nt * 2 + 1] = __ldg(bias + c + 1);
        if (bn) {
            float s0 = __ldg(gamma + c) * rsqrtf(__ldg(var + c) + 1e-5f);
            float s1 = __ldg(gamma + c + 1) * rsqrtf(__ldg(var + c + 1) + 1e-5f);
            scv[nt * 2] = s0;     shv[nt * 2]     = __ldg(beta + c) - __ldg(mean + c) * s0;
            scv[nt * 2 + 1] = s1; shv[nt * 2 + 1] = __ldg(beta + c + 1) - __ldg(mean + c + 1) * s1;
        }
    }

    // ldmatrix lane address components
    unsigned aoff = (unsigned)((wr * 32 + (lane & 15)) * ASTR_B + (lane >> 4) * 16);
    // B x4 ldmatrix covering nt-pairs: lanes 0-7 -> (nt, khalf0), 8-15 -> (nt, khalf1),
    // lanes 16-23 -> (nt+1, khalf0), 24-31 -> (nt+1, khalf1)
    int bnt_sub = (lane >> 3) & 1;       // which nt of the pair
    int bkh = (lane >> 4) & 1;           // wrong for this mapping; compute explicitly:
    // For x4: matrix index m = lane >> 3 (0..3). m0=(nt,k0), m1=(nt,k1), m2=(nt+1,k0), m3=(nt+1,k1)
    int bm = lane >> 3;
    int b_nt_off = (bm >> 1);            // 0 or 1 -> nt offset within pair
    int b_kh = bm & 1;                   // k half
    unsigned boff = (unsigned)((wc * 64 + b_nt_off * 8 + (lane & 7)) * ASTR_B + b_kh * 16);
    unsigned bH = sb + SM_WH + boff, bL = sb + SM_WL + boff;

    int bufi = 0;
    for (; tile < MTILES; tile += PERSIST_GRID, bufi ^= 1) {
        asm volatile("cp.async.wait_group 0;" ::: "memory");
        __syncthreads();
        int next = tile + PERSIST_GRID;
        if (next < MTILES) issue_A(Ah, Al, next * 128, sb + SM_ABUF(bufi ^ 1), tid);
        asm volatile("cp.async.commit_group;" ::: "memory");

        unsigned abase = sb + SM_ABUF(bufi);
        unsigned aH0 = abase + aoff, aH1 = aH0 + 16 * ASTR_B;
        unsigned aL0 = abase + MAT_B + aoff, aL1 = aL0 + 16 * ASTR_B;

        float acc[2][8][4];
        #pragma unroll
        for (int mt = 0; mt < 2; mt++)
            #pragma unroll
            for (int nt = 0; nt < 8; nt++)
                #pragma unroll
                for (int j = 0; j < 4; j++) acc[mt][nt][j] = 0.f;

        #pragma unroll
        for (int ks = 0; ks < 8; ks++) {
            unsigned kb = (unsigned)(ks * 32);            // k0 * 2 bytes
            unsigned ah[2][4], al[2][4], bhr[4][4], blr[4][4];
            ldsm4(ah[0], aH0 + kb);
            ldsm4(ah[1], aH1 + kb);
            ldsm4(al[0], aL0 + kb);
            ldsm4(al[1], aL1 + kb);
            #pragma unroll
            for (int np = 0; np < 4; np++) {              // nt pair {2np, 2np+1}
                ldsm4(bhr[np], bH + (unsigned)(np * 16 * ASTR_B) + kb);
                ldsm4(blr[np], bL + (unsigned)(np * 16 * ASTR_B) + kb);
            }
            // combo-major: 16 independent MMAs per combo; same-acc reuse is 16 issues apart
            #pragma unroll
            for (int mt = 0; mt < 2; mt++)
                #pragma unroll
                for (int nt = 0; nt < 8; nt++)
                    mma_bf16(acc[mt][nt], ah[mt], &bhr[nt >> 1][(nt & 1) * 2]);
            #pragma unroll
            for (int mt = 0; mt < 2; mt++)
                #pragma unroll
                for (int nt = 0; nt < 8; nt++)
                    mma_bf16(acc[mt][nt], ah[mt], &blr[nt >> 1][(nt & 1) * 2]);
            #pragma unroll
            for (int mt = 0; mt < 2; mt++)
                #pragma unroll
                for (int nt = 0; nt < 8; nt++)
                    mma_bf16(acc[mt][nt], al[mt], &bhr[nt >> 1][(nt & 1) * 2]);
        }

        // epilogue: C frag m16n8 -> rows quad, quad+8; cols qi*2, qi*2+1
        int row0 = tile * 128;
        #pragma unroll
        for (int mt = 0; mt < 2; mt++) {
            int r0 = row0 + wr * 32 + mt * 16 + quad;
            #pragma unroll
            for (int half = 0; half < 2; half++) {
                int r = r0 + half * 8;
                if (r >= N_NODES) continue;
                #pragma unroll
                for (int nt = 0; nt < 8; nt++) {
                    int c = wc * 64 + nt * 8 + qi * 2;
                    float d0 = acc[mt][nt][half * 2], d1 = acc[mt][nt][half * 2 + 1];
                    float v0 = fmaxf(d0 + bcol[nt * 2], 0.f);
                    float v1 = fmaxf(d1 + bcol[nt * 2 + 1], 0.f);
                    if (outf) {
                        if (bn) {
                            v0 = v0 * scv[nt * 2] + shv[nt * 2];
                            v1 = v1 * scv[nt * 2 + 1] + shv[nt * 2 + 1];
                        }
                        *(float2*)(outf + (long long)r * 128 + c) = make_float2(v0, v1);
                    } else {
                        float h0 = __bfloat162float(__float2bfloat16(v0));
                        float h1 = __bfloat162float(__float2bfloat16(v1));
                        *(unsigned*)(outh + (long long)r * 128 + c) = pack_bf(h0, h1);
                        *(unsigned*)(outl + (long long)r * 128 + c) = pack_bf(v0 - h0, v1 - h1);
                    }
                }
            }
        }
    }
}

// ---------------- mean pool per graph (batch sorted) + scratch reset tail ----------------
__device__ __forceinline__ int lower_bound_batch(const void* batch, long long key, int is64) {
    int lo = 0, hi = N_NODES;
    while (lo < hi) {
        int mid = (lo + hi) >> 1;
        long long v = load_idx(batch, mid, is64);
        if (v < key) lo = mid + 1; else hi = mid;
    }
    return lo;
}

__global__ void k_pool(const float* __restrict__ x, const void* __restrict__ batch) {
    int g = blockIdx.x;
    int f = threadIdx.x;
    __shared__ int s_beg, s_end;
    if (f == 0) {
        int is64 = g_is64;
        s_beg = lower_bound_batch(batch, g, is64);
        s_end = lower_bound_batch(batch, g + 1, is64);
    }
    __syncthreads();
    int beg = s_beg, end = s_end;
    float s = 0.f;
    for (int r = beg; r < end; r++) s += x[(long long)r * HID + f];
    float cnt = (float)(end - beg);
    g_pooled[g * HID + f] = s / fmaxf(cnt, 1.0f);

    // tail: reset CSR scratch + barriers for the next graph replay
    int gt = g * HID + f;
    for (int i = gt; i < N_NODES + 1; i += N_GRAPHS * HID) g_rowoff[i] = 0;
    if (gt < SCAN_B) g_bflag[gt] = 0;
    if (gt == 0) g_gbar = 0;
}

// ---------------- head: relu(pooled@W1+b1) @ W2 + b2, log_softmax ----------------
__global__ void k_head(const float* __restrict__ W1, const float* __restrict__ b1,
                       const float* __restrict__ W2, const float* __restrict__ b2,
                       float* __restrict__ out) {
    int g = blockIdx.x;
    int t = threadIdx.x;
    __shared__ float sp[HID], sh[HID], sl[OUT_DIM];
    __shared__ float smax, slse;
    sp[t] = g_pooled[g * HID + t];
    __syncthreads();
    float acc = b1[t];
    #pragma unroll 8
    for (int k = 0; k < HID; k++) acc += sp[k] * W1[k * HID + t];
    sh[t] = fmaxf(acc, 0.f);
    __syncthreads();
    if (t < OUT_DIM) {
        float a = b2[t];
        #pragma unroll 8
        for (int k = 0; k < HID; k++) a += sh[k] * W2[k * OUT_DIM + t];
        sl[t] = a;
    }
    __syncthreads();
    if (t == 0) {
        float m = -1e30f;
        for (int o = 0; o < OUT_DIM; o++) m = fmaxf(m, sl[o]);
        float s = 0.f;
        for (int o = 0; o < OUT_DIM; o++) s += expf(sl[o] - m);
        smax = m; slse = logf(s);
    }
    __syncthreads();
    if (t < OUT_DIM) out[g * OUT_DIM + t] = sl[t] - smax - slse;
}

// ---------------- launch ----------------
extern "C" void kernel_launch(void* const* d_in, const int* in_sizes, int n_in,
                              void* d_out, int out_size) {
    const float* x      = (const float*)d_in[0];
    const void*  edge   = d_in[1];
    const void*  batch  = d_in[2];
    const float* W1s    = (const float*)d_in[3];
    const float* b1s    = (const float*)d_in[4];
    const float* W2s    = (const float*)d_in[5];
    const float* b2s    = (const float*)d_in[6];
    const float* gammas = (const float*)d_in[7];
    const float* betas  = (const float*)d_in[8];
    const float* means  = (const float*)d_in[9];
    const float* vars   = (const float*)d_in[10];
    const float* epsarr = (const float*)d_in[11];
    const float* lin1W  = (const float*)d_in[12];
    const float* lin1b  = (const float*)d_in[13];
    const float* lin2W  = (const float*)d_in[14];
    const float* lin2b  = (const float*)d_in[15];
    float* out = (float*)d_out;

    float *A;
    __nv_bfloat16 *Bh, *Bl, *Ch, *Cl, *Wth, *Wtl;
    cudaGetSymbolAddress((void**)&A,  g_A);
    cudaGetSymbolAddress((void**)&Bh, g_Bh);
    cudaGetSymbolAddress((void**)&Bl, g_Bl);
    cudaGetSymbolAddress((void**)&Ch, g_Ch);
    cudaGetSymbolAddress((void**)&Cl, g_Cl);
    cudaGetSymbolAddress((void**)&Wth, g_Wth);
    cudaGetSymbolAddress((void**)&Wtl, g_Wtl);

    cudaFuncSetAttribute(k_mma, cudaFuncAttributeMaxDynamicSharedMemorySize, SM_TOTAL);

    // CSR build + weight prep; fillagg fuses fill with layer-0 agg so that
    // k_mma is launch #4 (the ncu capture slot)
    k_count<<<EDGE_BLOCKS + WPREP_BLOCKS, 256>>>(edge, W1s, W2s);
    k_scanall<<<SCAN_B, 1024>>>();
    k_fillagg<<<FA_BLOCKS, FA_THREADS>>>(edge, x, Bh, Bl, epsarr);

    const int agg_blocks = (N_NODES * 32 + 255) / 256;

    for (int l = 0; l < N_LAYERS; l++) {
        if (l > 0)
            k_agg<<<agg_blocks, 256>>>(A, Bh, Bl, epsarr, l);
        // GEMM1: relu -> bf16 hi/lo
        k_mma<<<PERSIST_GRID, 256, SM_TOTAL>>>(
            Bh, Bl, Wth + (l * 2) * 16384, Wtl + (l * 2) * 16384,
            b1s + l * HID, nullptr, Ch, Cl,
            nullptr, nullptr, nullptr, nullptr);
        // GEMM2: relu + BN -> fp32
        k_mma<<<PERSIST_GRID, 256, SM_TOTAL>>>(
            Ch, Cl, Wth + (l * 2 + 1) * 16384, Wtl + (l * 2 + 1) * 16384,
            b2s + l * HID, A, nullptr, nullptr,
            gammas + l * HID, betas + l * HID, means + l * HID, vars + l * HID);
    }

    k_pool<<<N_GRAPHS, HID>>>(A, batch);
    k_head<<<N_GRAPHS, HID>>>(lin1W, lin1b, lin2W, lin2b, out);
}